// round 1
// baseline (speedup 1.0000x reference)
#include <cuda_runtime.h>
#include <cuda_bf16.h>
#include <cstdint>

#define BMAX   64
#define MA     96
#define NDIM   256
#define EPSF   1e-8f

// Scratch: scatter buffer for padded node scores [B, MAX_A].
// Device globals are legal (no dynamic allocation).
__device__ float g_sp[BMAX * MA];

// ---------------------------------------------------------------------------
// Kernel 0: zero the scatter buffer (invalid k positions must be exactly 0,
// matching the reference's zeros-init scatter target).
// ---------------------------------------------------------------------------
__global__ void zero_sp_kernel() {
    int t = blockIdx.x * blockDim.x + threadIdx.x;
    if (t < BMAX * MA) g_sp[t] = 0.0f;
}

// ---------------------------------------------------------------------------
// Kernel 1: scores = x @ W[0] + b[0], scattered into g_sp via pad_idx.
// One warp per node: 256 dims = 64 float4 = 2 float4 per lane, shfl reduce.
// ---------------------------------------------------------------------------
__global__ void score_scatter_kernel(const float* __restrict__ x,
                                     const float* __restrict__ W,
                                     const float* __restrict__ bscal,
                                     const int*   __restrict__ pad_idx,
                                     int total) {
    int gwarp = (blockIdx.x * blockDim.x + threadIdx.x) >> 5;
    int lane  = threadIdx.x & 31;
    if (gwarp >= total) return;

    const float4* xr = reinterpret_cast<const float4*>(x + (size_t)gwarp * NDIM);
    const float4* wr = reinterpret_cast<const float4*>(W);

    float s = 0.0f;
    #pragma unroll
    for (int i = 0; i < 2; i++) {
        float4 a  = xr[lane + i * 32];
        float4 ww = wr[lane + i * 32];
        s += a.x * ww.x + a.y * ww.y + a.z * ww.z + a.w * ww.w;
    }
    #pragma unroll
    for (int o = 16; o > 0; o >>= 1)
        s += __shfl_xor_sync(0xFFFFFFFFu, s, o);

    if (lane == 0)
        g_sp[pad_idx[gwarp]] = s + bscal[0];
}

// ---------------------------------------------------------------------------
// Kernel 2 (the 226 MB pass): one block per (b, i) slab [96 x 96].
// One warp per j-row; 32 lanes cover k in {lane, lane+32, lane+64}.
// All loads are full coalesced 128B transactions; slab is 36 KB contiguous.
// ---------------------------------------------------------------------------
__global__ __launch_bounds__(256) void path_avg_kernel(
        const float* __restrict__ paths,
        float*       __restrict__ out) {
    int bi = blockIdx.x;            // b * MA + i
    int b  = bi / MA;

    __shared__ float sp[MA];
    int t = threadIdx.x;
    if (t < MA) sp[t] = g_sp[b * MA + t];
    __syncthreads();

    int w    = t >> 5;
    int lane = t & 31;
    float s0 = sp[lane];
    float s1 = sp[lane + 32];
    float s2 = sp[lane + 64];

    const float* base = paths + (size_t)bi * (MA * MA);
    float*       orow = out   + (size_t)bi * MA;

    #pragma unroll
    for (int j = w; j < MA; j += 8) {
        const float* p = base + j * MA;
        float p0 = p[lane];
        float p1 = p[lane + 32];
        float p2 = p[lane + 64];

        float num = p0 * s0 + p1 * s1 + p2 * s2;
        float den = p0 + p1 + p2;

        #pragma unroll
        for (int o = 16; o > 0; o >>= 1) {
            num += __shfl_xor_sync(0xFFFFFFFFu, num, o);
            den += __shfl_xor_sync(0xFFFFFFFFu, den, o);
        }
        if (lane == 0)
            orow[j] = num / (den + EPSF);
    }
}

// ---------------------------------------------------------------------------
// Launch. Inputs (metadata order): x, W, b, paths, pad_idx.
// ---------------------------------------------------------------------------
extern "C" void kernel_launch(void* const* d_in, const int* in_sizes, int n_in,
                              void* d_out, int out_size) {
    const float* x       = (const float*)d_in[0];
    const float* W       = (const float*)d_in[1];
    const float* bscal   = (const float*)d_in[2];
    const float* paths   = (const float*)d_in[3];
    const int*   pad_idx = (const int*)d_in[4];
    float*       out     = (float*)d_out;

    int total = in_sizes[4];   // number of nodes (== in_sizes[0] / NDIM)

    // 0: zero scatter buffer
    zero_sp_kernel<<<(BMAX * MA + 255) / 256, 256>>>();

    // 1: scores + scatter (one warp per node)
    int threads_needed = total * 32;
    int blocks1 = (threads_needed + 255) / 256;
    score_scatter_kernel<<<blocks1, 256>>>(x, W, bscal, pad_idx, total);

    // 2: main fused pass over paths
    path_avg_kernel<<<BMAX * MA, 256>>>(paths, out);
}

// round 3
// speedup vs baseline: 1.5383x; 1.5383x over previous
#include <cuda_runtime.h>
#include <cuda_bf16.h>
#include <cstdint>

#define BMAX   64
#define MA     96
#define NDIM   256
#define EPSF   1e-8f
#define SLAB_F4 2304          // 96*96/4 float4 per slab

// Scatter buffer for padded node scores [B, MAX_A].
// Zero-initialized at module load; invalid positions are never written and
// stay 0 (and paths is 0 there anyway), so no explicit zeroing kernel needed.
__device__ float g_sp[BMAX * MA];

// ---------------------------------------------------------------------------
// Kernel 1: scores = x @ W[0] + b[0], scattered into g_sp via pad_idx.
// One warp per node: 256 dims = 2 float4 per lane, shfl reduce.
// ---------------------------------------------------------------------------
__global__ void score_scatter_kernel(const float* __restrict__ x,
                                     const float* __restrict__ W,
                                     const float* __restrict__ bscal,
                                     const int*   __restrict__ pad_idx,
                                     int total) {
    int gwarp = (blockIdx.x * blockDim.x + threadIdx.x) >> 5;
    int lane  = threadIdx.x & 31;
    if (gwarp >= total) return;

    const float4* xr = reinterpret_cast<const float4*>(x + (size_t)gwarp * NDIM);
    const float4* wr = reinterpret_cast<const float4*>(W);

    float s = 0.0f;
    #pragma unroll
    for (int i = 0; i < 2; i++) {
        float4 a  = xr[lane + i * 32];
        float4 ww = wr[lane + i * 32];
        s += a.x * ww.x + a.y * ww.y + a.z * ww.z + a.w * ww.w;
    }
    #pragma unroll
    for (int o = 16; o > 0; o >>= 1)
        s += __shfl_xor_sync(0xFFFFFFFFu, s, o);

    if (lane == 0)
        g_sp[pad_idx[gwarp]] = s + bscal[0];
}

// ---------------------------------------------------------------------------
// Kernel 2 (the 226 MB pass): one block per (b, i) slab [96 x 96].
// Phase A: 256 threads stage the slab into smem with 9 independent, fully
//          coalesced float4 loads each (max MLP), XOR-swizzled layout.
// Phase B: thread j (j < 96) reduces row j with 24 conflict-free LDS.128 +
//          broadcast sp float4 reads. Zero shuffles. One STG per thread.
// ---------------------------------------------------------------------------
__global__ __launch_bounds__(256) void path_avg_kernel(
        const float4* __restrict__ paths4,
        float*        __restrict__ out) {
    __shared__ float s_slab[MA * MA];   // 36 KB, swizzled rows
    __shared__ float s_sp[MA];

    int bi = blockIdx.x;                // b * MA + i
    int b  = bi / MA;
    int t  = threadIdx.x;

    if (t < MA) s_sp[t] = g_sp[b * MA + t];

    const float4* src = paths4 + (size_t)bi * SLAB_F4;
    #pragma unroll
    for (int i = 0; i < 9; i++) {
        int f = t + i * 256;            // float4 index within slab [0, 2304)
        float4 v = src[f];
        int r = f / 24;                 // row (j)
        int c = f - r * 24;             // float4 column within row [0, 24)
        int cs = c ^ (r & 7);           // bank swizzle (stays in [0, 24))
        *reinterpret_cast<float4*>(&s_slab[r * MA + cs * 4]) = v;
    }
    __syncthreads();

    if (t < MA) {
        const float* row = &s_slab[t * MA];
        int sw = t & 7;
        float num = 0.0f, den = 0.0f;
        #pragma unroll
        for (int c = 0; c < 24; c++) {
            float4 p = *reinterpret_cast<const float4*>(&row[(c ^ sw) * 4]);
            float4 s = *reinterpret_cast<const float4*>(&s_sp[c * 4]);
            num += p.x * s.x + p.y * s.y + p.z * s.z + p.w * s.w;
            den += (p.x + p.y) + (p.z + p.w);
        }
        out[(size_t)bi * MA + t] = num / (den + EPSF);
    }
}

// ---------------------------------------------------------------------------
// Launch. Inputs (metadata order): x, W, b, paths, pad_idx.
// ---------------------------------------------------------------------------
extern "C" void kernel_launch(void* const* d_in, const int* in_sizes, int n_in,
                              void* d_out, int out_size) {
    const float*  x       = (const float*)d_in[0];
    const float*  W       = (const float*)d_in[1];
    const float*  bscal   = (const float*)d_in[2];
    const float4* paths4  = (const float4*)d_in[3];
    const int*    pad_idx = (const int*)d_in[4];
    float*        out     = (float*)d_out;

    int total = in_sizes[4];   // number of valid nodes

    // 1: scores + scatter (one warp per node)
    int blocks1 = (total * 32 + 255) / 256;
    score_scatter_kernel<<<blocks1, 256>>>(x, W, bscal, pad_idx, total);

    // 2: main fused pass over paths
    path_avg_kernel<<<BMAX * MA, 256>>>(paths4, out);
}